// round 7
// baseline (speedup 1.0000x reference)
#include <cuda_runtime.h>
#include <cuda_fp16.h>
#include <cstdint>
#include <cstddef>

// ============================================================
// UUPBitLinear: out = round(clip(x @ (sign(W-mean)*gamma) + bias, -1, 1)*7)/7
//   x: [65536, 512] fp32, W: [512, 512] fp32, bias: [512] fp32
//
// HMMA mma.sync path. gamma factored out -> B operand is exact ternary fp16
// S^T. x pre-split into hi/lo fp16; GEMM = 3-stage cp.async pipelined fp16
// MMA with fp32 accumulate.
// R6: CTA 128x64, 4 warps, warp tile 32x64 -> A smem-read once per CTA
//     (crossbar below tensor floor), 3 CTAs/SM, no register spills.
// ============================================================

#define M_TOTAL 65536
#define N_TOTAL 512
#define K_TOTAL 512

#define BM 128
#define BN 64
#define BK 32
#define KB_STEPS (K_TOTAL / BK)   // 16
#define STAGES 3

// dynamic smem: [0,256) bias; stages at 1024 + s*20480
//   A_hi: 128 rows x 64B = 8192 ; A_lo: 8192 ; B: 64 rows x 64B = 4096
#define OFF_BIAS   0
#define STAGE_SZ   20480
#define OFF_AHI(s) (1024 + (s) * STAGE_SZ)
#define OFF_ALO(s) (1024 + (s) * STAGE_SZ + 8192)
#define OFF_BT(s)  (1024 + (s) * STAGE_SZ + 16384)
#define SMEM_TOTAL (1024 + STAGES * STAGE_SZ)   // 62464 -> 3 CTAs/SM

// ---- device scratch (allocation-free) ----
__device__ float  g_part_sum[512];
__device__ float  g_part_abs[512];
__device__ float  g_mean;
__device__ float  g_gamma;
__device__ __half g_ST[N_TOTAL * K_TOTAL];            // S^T: [N][K] ternary fp16
__device__ __half g_xhi[(size_t)M_TOTAL * K_TOTAL];   // 64 MB
__device__ __half g_xlo[(size_t)M_TOTAL * K_TOTAL];   // 64 MB

// ---- helpers ----
__device__ __forceinline__ uint32_t smem_u32(const void* p) {
    uint32_t a;
    asm("{ .reg .u64 t; cvta.to.shared.u64 t, %1; cvt.u32.u64 %0, t; }"
        : "=r"(a) : "l"(p));
    return a;
}

// rows are 64B (32 halfs); chunk = 16B unit (0..3), swizzled so ldmatrix's
// 8-row groups hit distinct banks (validated R3-R5).
__device__ __forceinline__ uint32_t sw_off(int row, int chunk) {
    return (uint32_t)(row * 64 + (((chunk ^ ((row >> 1) & 3)) & 3) << 4));
}

#define LDSM_X4(r0, r1, r2, r3, addr)                                      \
    asm volatile("ldmatrix.sync.aligned.m8n8.x4.shared.b16 "               \
                 "{%0,%1,%2,%3}, [%4];"                                    \
                 : "=r"(r0), "=r"(r1), "=r"(r2), "=r"(r3) : "r"(addr))

#define MMA16816(d, a0, a1, a2, a3, b0, b1)                                \
    asm volatile("mma.sync.aligned.m16n8k16.row.col.f32.f16.f16.f32 "      \
                 "{%0,%1,%2,%3}, {%4,%5,%6,%7}, {%8,%9}, {%0,%1,%2,%3};"   \
                 : "+f"((d)[0]), "+f"((d)[1]), "+f"((d)[2]), "+f"((d)[3])  \
                 : "r"(a0), "r"(a1), "r"(a2), "r"(a3), "r"(b0), "r"(b1))

#define CP16(smaddr, gptr)                                                 \
    asm volatile("cp.async.cg.shared.global [%0], [%1], 16;"               \
                 :: "r"(smaddr), "l"(__cvta_generic_to_global(gptr)) : "memory")

#define CP_COMMIT() asm volatile("cp.async.commit_group;" ::: "memory")
#define CP_WAIT1()  asm volatile("cp.async.wait_group 1;" ::: "memory")

__device__ __forceinline__ uint32_t pack_h2(__half a, __half b) {
    __half2 h = __halves2half2(a, b);
    return *reinterpret_cast<uint32_t*>(&h);
}

__device__ __forceinline__ float quantize(float y) {
    y = fminf(fmaxf(y, -1.0f), 1.0f);
    return rintf(y * 7.0f) * (1.0f / 7.0f);   // round-half-even == jnp.round
}

// ---- prep 1: deterministic per-row reduction of W ----
__global__ void reduce_rows(const float* __restrict__ w) {
    __shared__ float ss[256], sa[256];
    int r = blockIdx.x, t = threadIdx.x;
    float v0 = w[r * 512 + t];
    float v1 = w[r * 512 + t + 256];
    ss[t] = v0 + v1;
    sa[t] = fabsf(v0) + fabsf(v1);
    __syncthreads();
    #pragma unroll
    for (int o = 128; o > 0; o >>= 1) {
        if (t < o) { ss[t] += ss[t + o]; sa[t] += sa[t + o]; }
        __syncthreads();
    }
    if (t == 0) { g_part_sum[r] = ss[0]; g_part_abs[r] = sa[0]; }
}

// ---- prep 2: final deterministic reduce -> mean, gamma ----
__global__ void reduce_final() {
    __shared__ float ss[256], sa[256];
    int t = threadIdx.x;
    ss[t] = g_part_sum[t] + g_part_sum[t + 256];
    sa[t] = g_part_abs[t] + g_part_abs[t + 256];
    __syncthreads();
    #pragma unroll
    for (int o = 128; o > 0; o >>= 1) {
        if (t < o) { ss[t] += ss[t + o]; sa[t] += sa[t + o]; }
        __syncthreads();
    }
    if (t == 0) {
        g_mean  = ss[0] * (1.0f / 262144.0f);
        g_gamma = sa[0] * (1.0f / 262144.0f);
    }
}

// ---- prep 3: pack S^T[n][k] = sign(W[k][n] - mean) as fp16 ----
__global__ void pack_signs(const float* __restrict__ w) {
    int n = blockIdx.x;
    int k = threadIdx.x;
    float d = w[k * 512 + n] - g_mean;
    float s = (d > 0.0f) ? 1.0f : ((d < 0.0f) ? -1.0f : 0.0f);
    g_ST[n * 512 + k] = __float2half(s);
}

// ---- prep 4: split x into fp16 hi/lo (exact 2-term decomposition) ----
__global__ void __launch_bounds__(256)
split_x(const float* __restrict__ x) {
    size_t i = ((size_t)blockIdx.x * 256 + threadIdx.x) * 8;
    float4 a = *reinterpret_cast<const float4*>(x + i);
    float4 b = *reinterpret_cast<const float4*>(x + i + 4);
    float f[8] = {a.x, a.y, a.z, a.w, b.x, b.y, b.z, b.w};
    uint32_t hi[4], lo[4];
    #pragma unroll
    for (int j = 0; j < 4; j++) {
        float u = f[2 * j], v = f[2 * j + 1];
        __half hu = __float2half_rn(u), hv = __float2half_rn(v);
        __half lu = __float2half_rn(u - __half2float(hu));
        __half lv = __float2half_rn(v - __half2float(hv));
        hi[j] = pack_h2(hu, hv);
        lo[j] = pack_h2(lu, lv);
    }
    *reinterpret_cast<uint4*>(g_xhi + i) = make_uint4(hi[0], hi[1], hi[2], hi[3]);
    *reinterpret_cast<uint4*>(g_xlo + i) = make_uint4(lo[0], lo[1], lo[2], lo[3]);
}

// ---- main GEMM: 4 warps, warp tile 32x64, 3-stage cp.async pipeline ----
__global__ void __launch_bounds__(128, 3)
bitlinear_gemm(const float* __restrict__ bias, float* __restrict__ out) {
    extern __shared__ unsigned char smem[];
    const uint32_t sb = smem_u32(smem);
    const int tid = threadIdx.x;
    const int wid = tid >> 5;         // warp_m: 4 warps along M (32 rows each)
    const int lid = tid & 31;
    const int n0 = blockIdx.x * BN;   // grid.x = 8  (n fastest -> L2 reuse of x)
    const int m0 = blockIdx.y * BM;   // grid.y = 512

    if (tid < BN) {
        reinterpret_cast<float*>(smem + OFF_BIAS)[tid] = bias[n0 + tid];
    }

    // staging roles (128 threads):
    //   A: thread tid owns row tid (all 4 chunks of 64B) for hi and lo
    //   B: thread -> (row = tid>>1, 2 chunks)
    const int brow = tid >> 1;
    const int bc2  = (tid & 1) * 2;
    const __half* ah_base = g_xhi + (size_t)(m0 + tid) * K_TOTAL;
    const __half* al_base = g_xlo + (size_t)(m0 + tid) * K_TOTAL;
    const __half* b_base  = g_ST  + (size_t)(n0 + brow) * K_TOTAL + bc2 * 8;
    const uint32_t asw0 = sw_off(tid, 0);
    const uint32_t asw1 = sw_off(tid, 1);
    const uint32_t asw2 = sw_off(tid, 2);
    const uint32_t asw3 = sw_off(tid, 3);
    const uint32_t bsw0 = sw_off(brow, bc2 + 0);
    const uint32_t bsw1 = sw_off(brow, bc2 + 1);

    auto issue_stage = [&](int kb) {
        if (kb < KB_STEPS) {
            const int buf = kb % STAGES;
            const __half* ah = ah_base + kb * BK;
            const __half* al = al_base + kb * BK;
            const __half* bp = b_base  + kb * BK;
            CP16(sb + OFF_AHI(buf) + asw0, ah);
            CP16(sb + OFF_AHI(buf) + asw1, ah + 8);
            CP16(sb + OFF_AHI(buf) + asw2, ah + 16);
            CP16(sb + OFF_AHI(buf) + asw3, ah + 24);
            CP16(sb + OFF_ALO(buf) + asw0, al);
            CP16(sb + OFF_ALO(buf) + asw1, al + 8);
            CP16(sb + OFF_ALO(buf) + asw2, al + 16);
            CP16(sb + OFF_ALO(buf) + asw3, al + 24);
            CP16(sb + OFF_BT(buf)  + bsw0, bp);
            CP16(sb + OFF_BT(buf)  + bsw1, bp + 8);
        }
        CP_COMMIT();
    };

    issue_stage(0);
    issue_stage(1);

    float acc[2][8][4];
    #pragma unroll
    for (int i = 0; i < 2; i++)
        #pragma unroll
        for (int j = 0; j < 8; j++)
            #pragma unroll
            for (int c = 0; c < 4; c++) acc[i][j][c] = 0.0f;

    const int fr  = lid & 15;     // ldmatrix row within 16
    const int fch = lid >> 4;     // k-half select

    for (int kb = 0; kb < KB_STEPS; kb++) {
        CP_WAIT1();               // stage kb complete (1 newer group in flight)
        __syncthreads();          // stage kb-1 fully consumed by all warps
        issue_stage(kb + 2);      // refill buf (kb-1)%3 — safe post-barrier

        const int buf = kb % STAGES;
        const uint32_t ahi = sb + OFF_AHI(buf);
        const uint32_t alo = sb + OFF_ALO(buf);
        const uint32_t bsm = sb + OFF_BT(buf);

        #pragma unroll
        for (int ks = 0; ks < 2; ks++) {
            uint32_t a_hi[2][4], a_lo[2][4], bq[4][4];
            #pragma unroll
            for (int mt = 0; mt < 2; mt++) {
                int row = wid * 32 + mt * 16 + fr;
                uint32_t o = sw_off(row, ks * 2 + fch);
                LDSM_X4(a_hi[mt][0], a_hi[mt][1], a_hi[mt][2], a_hi[mt][3], ahi + o);
                LDSM_X4(a_lo[mt][0], a_lo[mt][1], a_lo[mt][2], a_lo[mt][3], alo + o);
            }
            #pragma unroll
            for (int p = 0; p < 4; p++) {   // 2 n-tiles per ldmatrix.x4
                int row = p * 16 + fr;
                uint32_t o = sw_off(row, ks * 2 + fch);
                LDSM_X4(bq[p][0], bq[p][1], bq[p][2], bq[p][3], bsm + o);
            }
            #pragma unroll
            for (int mt = 0; mt < 2; mt++) {
                #pragma unroll
                for (int nt = 0; nt < 8; nt++) {
                    uint32_t b0 = bq[nt >> 1][nt & 1];
                    uint32_t b1 = bq[nt >> 1][2 + (nt & 1)];
                    MMA16816(acc[mt][nt], a_hi[mt][0], a_hi[mt][1], a_hi[mt][2], a_hi[mt][3], b0, b1);
                    MMA16816(acc[mt][nt], a_lo[mt][0], a_lo[mt][1], a_lo[mt][2], a_lo[mt][3], b0, b1);
                }
            }
        }
    }

    // ---- epilogue: scale by gamma, add bias, quantize, store ----
    const float gamma = g_gamma;
    const float* bias_s = reinterpret_cast<const float*>(smem + OFF_BIAS);
    #pragma unroll
    for (int mt = 0; mt < 2; mt++) {
        int row0 = m0 + wid * 32 + mt * 16 + (lid >> 2);
        #pragma unroll
        for (int nt = 0; nt < 8; nt++) {
            int coln = nt * 8 + (lid & 3) * 2;
            float b0 = bias_s[coln], b1 = bias_s[coln + 1];
            float2 v0, v1;
            v0.x = quantize(acc[mt][nt][0] * gamma + b0);
            v0.y = quantize(acc[mt][nt][1] * gamma + b1);
            v1.x = quantize(acc[mt][nt][2] * gamma + b0);
            v1.y = quantize(acc[mt][nt][3] * gamma + b1);
            *reinterpret_cast<float2*>(out + (size_t)row0 * N_TOTAL + n0 + coln) = v0;
            *reinterpret_cast<float2*>(out + (size_t)(row0 + 8) * N_TOTAL + n0 + coln) = v1;
        }
    }
}

// ---- harness entry ----
extern "C" void kernel_launch(void* const* d_in, const int* in_sizes, int n_in,
                              void* d_out, int out_size) {
    const float* x    = (const float*)d_in[0];
    const float* w    = (const float*)d_in[1];
    const float* bias = (const float*)d_in[2];
    float* out = (float*)d_out;

    cudaFuncSetAttribute(bitlinear_gemm,
                         cudaFuncAttributeMaxDynamicSharedMemorySize, SMEM_TOTAL);

    reduce_rows<<<512, 256>>>(w);
    reduce_final<<<1, 256>>>();
    pack_signs<<<512, 512>>>(w);
    split_x<<<(M_TOTAL * K_TOTAL) / (8 * 256), 256>>>(x);

    dim3 grid(N_TOTAL / BN, M_TOTAL / BM);   // (8, 512): n fastest
    bitlinear_gemm<<<grid, 128, SMEM_TOTAL>>>(bias, out);
}

// round 9
// speedup vs baseline: 1.5160x; 1.5160x over previous
#include <cuda_runtime.h>
#include <cuda_fp16.h>
#include <cstdint>
#include <cstddef>

// ============================================================
// UUPBitLinear: out = round(clip(x @ (sign(W-mean)*gamma) + bias, -1, 1)*7)/7
//   x: [65536, 512] fp32, W: [512, 512] fp32, bias: [512] fp32
//
// HMMA mma.sync path. gamma factored out -> B operand is exact ternary fp16
// S^T. x pre-split into hi/lo fp16; GEMM = 3-stage cp.async pipelined fp16
// MMA with fp32 accumulate. (R5 GEMM config = best measured: 262 us.)
// R7: launch order reshuffled so the GEMM is the 4th launch (ncu captures
//     launch #4) -> get GEMM profile; W-reduce fused into one CTA.
// ============================================================

#define M_TOTAL 65536
#define N_TOTAL 512
#define K_TOTAL 512

#define BM 128
#define BN 64
#define BK 32
#define KB_STEPS (K_TOTAL / BK)   // 16
#define STAGES 3

// dynamic smem: [0,256) bias; stages at 1024 + s*20480
//   A_hi: 128 rows x 64B = 8192 ; A_lo: 8192 ; B: 64 rows x 64B = 4096
#define OFF_BIAS   0
#define STAGE_SZ   20480
#define OFF_AHI(s) (1024 + (s) * STAGE_SZ)
#define OFF_ALO(s) (1024 + (s) * STAGE_SZ + 8192)
#define OFF_BT(s)  (1024 + (s) * STAGE_SZ + 16384)
#define SMEM_TOTAL (1024 + STAGES * STAGE_SZ)   // 62464 -> 3 CTAs/SM

// ---- device scratch (allocation-free) ----
__device__ float  g_mean;
__device__ float  g_gamma;
__device__ __half g_ST[N_TOTAL * K_TOTAL];            // S^T: [N][K] ternary fp16
__device__ __half g_xhi[(size_t)M_TOTAL * K_TOTAL];   // 64 MB
__device__ __half g_xlo[(size_t)M_TOTAL * K_TOTAL];   // 64 MB

// ---- helpers ----
__device__ __forceinline__ uint32_t smem_u32(const void* p) {
    uint32_t a;
    asm("{ .reg .u64 t; cvta.to.shared.u64 t, %1; cvt.u32.u64 %0, t; }"
        : "=r"(a) : "l"(p));
    return a;
}

// rows are 64B (32 halfs); chunk = 16B unit (0..3), swizzled so ldmatrix's
// 8-row groups hit distinct banks (validated R3-R6).
__device__ __forceinline__ uint32_t sw_off(int row, int chunk) {
    return (uint32_t)(row * 64 + (((chunk ^ ((row >> 1) & 3)) & 3) << 4));
}

#define LDSM_X4(r0, r1, r2, r3, addr)                                      \
    asm volatile("ldmatrix.sync.aligned.m8n8.x4.shared.b16 "               \
                 "{%0,%1,%2,%3}, [%4];"                                    \
                 : "=r"(r0), "=r"(r1), "=r"(r2), "=r"(r3) : "r"(addr))

#define MMA16816(d, a0, a1, a2, a3, b0, b1)                                \
    asm volatile("mma.sync.aligned.m16n8k16.row.col.f32.f16.f16.f32 "      \
                 "{%0,%1,%2,%3}, {%4,%5,%6,%7}, {%8,%9}, {%0,%1,%2,%3};"   \
                 : "+f"((d)[0]), "+f"((d)[1]), "+f"((d)[2]), "+f"((d)[3])  \
                 : "r"(a0), "r"(a1), "r"(a2), "r"(a3), "r"(b0), "r"(b1))

#define CP16(smaddr, gptr)                                                 \
    asm volatile("cp.async.cg.shared.global [%0], [%1], 16;"               \
                 :: "r"(smaddr), "l"(__cvta_generic_to_global(gptr)) : "memory")

#define CP_COMMIT() asm volatile("cp.async.commit_group;" ::: "memory")
#define CP_WAIT1()  asm volatile("cp.async.wait_group 1;" ::: "memory")

__device__ __forceinline__ uint32_t pack_h2(__half a, __half b) {
    __half2 h = __halves2half2(a, b);
    return *reinterpret_cast<uint32_t*>(&h);
}

__device__ __forceinline__ float quantize(float y) {
    y = fminf(fmaxf(y, -1.0f), 1.0f);
    return rintf(y * 7.0f) * (1.0f / 7.0f);   // round-half-even == jnp.round
}

// ---- prep 1 (fused): deterministic full reduction of W -> mean, gamma ----
__global__ void __launch_bounds__(1024)
reduce_w(const float* __restrict__ w) {
    __shared__ float ss[1024], sa[1024];
    const int t = threadIdx.x;
    float s = 0.0f, a = 0.0f;
    // fixed order: thread t accumulates elements t, t+1024, ... (256 each)
    #pragma unroll 8
    for (int i = t; i < 512 * 512; i += 1024) {
        float v = w[i];
        s += v;
        a += fabsf(v);
    }
    ss[t] = s; sa[t] = a;
    __syncthreads();
    #pragma unroll
    for (int o = 512; o > 0; o >>= 1) {
        if (t < o) { ss[t] += ss[t + o]; sa[t] += sa[t + o]; }
        __syncthreads();
    }
    if (t == 0) {
        g_mean  = ss[0] * (1.0f / 262144.0f);
        g_gamma = sa[0] * (1.0f / 262144.0f);
    }
}

// ---- prep 2: pack S^T[n][k] = sign(W[k][n] - mean) as fp16 ----
__global__ void pack_signs(const float* __restrict__ w) {
    int n = blockIdx.x;
    int k = threadIdx.x;
    float d = w[k * 512 + n] - g_mean;
    float s = (d > 0.0f) ? 1.0f : ((d < 0.0f) ? -1.0f : 0.0f);
    g_ST[n * 512 + k] = __float2half(s);
}

// ---- prep 3: split x into fp16 hi/lo (exact 2-term decomposition) ----
__global__ void __launch_bounds__(256)
split_x(const float* __restrict__ x) {
    size_t i = ((size_t)blockIdx.x * 256 + threadIdx.x) * 8;
    float4 a = *reinterpret_cast<const float4*>(x + i);
    float4 b = *reinterpret_cast<const float4*>(x + i + 4);
    float f[8] = {a.x, a.y, a.z, a.w, b.x, b.y, b.z, b.w};
    uint32_t hi[4], lo[4];
    #pragma unroll
    for (int j = 0; j < 4; j++) {
        float u = f[2 * j], v = f[2 * j + 1];
        __half hu = __float2half_rn(u), hv = __float2half_rn(v);
        __half lu = __float2half_rn(u - __half2float(hu));
        __half lv = __float2half_rn(v - __half2float(hv));
        hi[j] = pack_h2(hu, hv);
        lo[j] = pack_h2(lu, lv);
    }
    *reinterpret_cast<uint4*>(g_xhi + i) = make_uint4(hi[0], hi[1], hi[2], hi[3]);
    *reinterpret_cast<uint4*>(g_xlo + i) = make_uint4(lo[0], lo[1], lo[2], lo[3]);
}

// ---- main GEMM (R5 config): 8 warps, warp 32x32, 3-stage cp.async ----
__global__ void __launch_bounds__(256, 3)
bitlinear_gemm(const float* __restrict__ bias, float* __restrict__ out) {
    extern __shared__ unsigned char smem[];
    const uint32_t sb = smem_u32(smem);
    const int tid = threadIdx.x;
    const int wid = tid >> 5;
    const int lid = tid & 31;
    const int warp_m = wid & 3;       // 4 warps along M (32 rows each)
    const int warp_n = wid >> 2;      // 2 warps along N (32 cols each)
    const int n0 = blockIdx.x * BN;   // grid.x = 8  (n fastest -> L2 reuse of x)
    const int m0 = blockIdx.y * BM;   // grid.y = 512

    if (tid < BN) {
        reinterpret_cast<float*>(smem + OFF_BIAS)[tid] = bias[n0 + tid];
    }

    // staging roles:
    //   A: thread -> (row = tid>>1, chunk pair cp = tid&1): 2 CP16 per buffer
    //   B: thread -> (row = tid>>2, chunk = tid&3): 1 CP16 per buffer
    const int arow = tid >> 1;
    const int acp  = tid & 1;
    const int brow = tid >> 2;
    const int bch  = tid & 3;
    const __half* ah_base = g_xhi + (size_t)(m0 + arow) * K_TOTAL + acp * 16;
    const __half* al_base = g_xlo + (size_t)(m0 + arow) * K_TOTAL + acp * 16;
    const __half* b_base  = g_ST  + (size_t)(n0 + brow) * K_TOTAL + bch * 8;
    const uint32_t asw0 = sw_off(arow, acp * 2 + 0);
    const uint32_t asw1 = sw_off(arow, acp * 2 + 1);
    const uint32_t bsw  = sw_off(brow, bch);

    auto issue_stage = [&](int kb) {
        if (kb < KB_STEPS) {
            const int buf = kb % STAGES;
            const __half* ah = ah_base + kb * BK;
            const __half* al = al_base + kb * BK;
            CP16(sb + OFF_AHI(buf) + asw0, ah);
            CP16(sb + OFF_AHI(buf) + asw1, ah + 8);
            CP16(sb + OFF_ALO(buf) + asw0, al);
            CP16(sb + OFF_ALO(buf) + asw1, al + 8);
            CP16(sb + OFF_BT(buf)  + bsw,  b_base + kb * BK);
        }
        CP_COMMIT();
    };

    issue_stage(0);
    issue_stage(1);

    float acc[2][4][4];
    #pragma unroll
    for (int i = 0; i < 2; i++)
        #pragma unroll
        for (int j = 0; j < 4; j++)
            #pragma unroll
            for (int c = 0; c < 4; c++) acc[i][j][c] = 0.0f;

    const int fr  = lid & 15;     // ldmatrix row within 16
    const int fch = lid >> 4;     // k-half select

    for (int kb = 0; kb < KB_STEPS; kb++) {
        CP_WAIT1();               // stage kb complete (1 newer group in flight)
        __syncthreads();          // stage kb-1 fully consumed by all warps
        issue_stage(kb + 2);      // refill buf (kb-1)%3 — safe post-barrier

        const int buf = kb % STAGES;
        const uint32_t ahi = sb + OFF_AHI(buf);
        const uint32_t alo = sb + OFF_ALO(buf);
        const uint32_t bsm = sb + OFF_BT(buf);

        #pragma unroll
        for (int ks = 0; ks < 2; ks++) {
            uint32_t a_hi[2][4], a_lo[2][4], bq[2][4];
            #pragma unroll
            for (int mt = 0; mt < 2; mt++) {
                int row = warp_m * 32 + mt * 16 + fr;
                uint32_t o = sw_off(row, ks * 2 + fch);
                LDSM_X4(a_hi[mt][0], a_hi[mt][1], a_hi[mt][2], a_hi[mt][3], ahi + o);
                LDSM_X4(a_lo[mt][0], a_lo[mt][1], a_lo[mt][2], a_lo[mt][3], alo + o);
            }
            #pragma unroll
            for (int p = 0; p < 2; p++) {   // 2 n-tiles per ldmatrix.x4
                int row = warp_n * 32 + p * 16 + fr;
                uint32_t o = sw_off(row, ks * 2 + fch);
                LDSM_X4(bq[p][0], bq[p][1], bq[p][2], bq[p][3], bsm + o);
            }
            #pragma unroll
            for (int mt = 0; mt < 2; mt++) {
                #pragma unroll
                for (int nt = 0; nt < 4; nt++) {
                    uint32_t b0 = bq[nt >> 1][nt & 1];
                    uint32_t b1 = bq[nt >> 1][2 + (nt & 1)];
                    MMA16816(acc[mt][nt], a_hi[mt][0], a_hi[mt][1], a_hi[mt][2], a_hi[mt][3], b0, b1);
                    MMA16816(acc[mt][nt], a_lo[mt][0], a_lo[mt][1], a_lo[mt][2], a_lo[mt][3], b0, b1);
                }
            }
        }
    }

    // ---- epilogue: scale by gamma, add bias, quantize, store ----
    const float gamma = g_gamma;
    const float* bias_s = reinterpret_cast<const float*>(smem + OFF_BIAS);
    #pragma unroll
    for (int mt = 0; mt < 2; mt++) {
        int row0 = m0 + warp_m * 32 + mt * 16 + (lid >> 2);
        #pragma unroll
        for (int nt = 0; nt < 4; nt++) {
            int coln = warp_n * 32 + nt * 8 + (lid & 3) * 2;
            float b0 = bias_s[coln], b1 = bias_s[coln + 1];
            float2 v0, v1;
            v0.x = quantize(acc[mt][nt][0] * gamma + b0);
            v0.y = quantize(acc[mt][nt][1] * gamma + b1);
            v1.x = quantize(acc[mt][nt][2] * gamma + b0);
            v1.y = quantize(acc[mt][nt][3] * gamma + b1);
            *reinterpret_cast<float2*>(out + (size_t)row0 * N_TOTAL + n0 + coln) = v0;
            *reinterpret_cast<float2*>(out + (size_t)(row0 + 8) * N_TOTAL + n0 + coln) = v1;
        }
    }
}

// ---- harness entry ----
extern "C" void kernel_launch(void* const* d_in, const int* in_sizes, int n_in,
                              void* d_out, int out_size) {
    const float* x    = (const float*)d_in[0];
    const float* w    = (const float*)d_in[1];
    const float* bias = (const float*)d_in[2];
    float* out = (float*)d_out;

    cudaFuncSetAttribute(bitlinear_gemm,
                         cudaFuncAttributeMaxDynamicSharedMemorySize, SMEM_TOTAL);

    // GEMM is the 4th launch -> ncu (-s 5 -c 1) captures it.
    reduce_w<<<1, 1024>>>(w);
    pack_signs<<<512, 512>>>(w);
    split_x<<<(M_TOTAL * K_TOTAL) / (8 * 256), 256>>>(x);

    dim3 grid(N_TOTAL / BN, M_TOTAL / BM);   // (8, 512): n fastest
    bitlinear_gemm<<<grid, 256, SMEM_TOTAL>>>(bias, out);
}